// round 15
// baseline (speedup 1.0000x reference)
#include <cuda_runtime.h>
#include <cuda_bf16.h>
#include <cstdint>

// ============================================================
// Problem constants
// ============================================================
#define MTOT 4096
#define NTOT 8192
#define KTOT 2048
#define NG   16
#define GSZ  (NTOT / NG)   // 512

// GEMM tiling
#define BM 128
#define BN 256
#define BK 32                    // bf16 K elements per stage
#define NCHUNK (KTOT / BK)       // 64
#define NSTAGE 4

// Tiled+swizzled scratch layout:
//   A block (per m-tile, per k-chunk): 128 rows x 128B ([64B hi | 64B lo]) = 16KB
//   B block (per n-tile, per k-chunk): 256 rows x 128B                     = 32KB
// Rows are SW128-swizzled IN GMEM so a linear bulk copy lands swizzled in SMEM.
#define A_BLK 16384
#define B_BLK 32768
#define STAGE_BYTES (A_BLK + B_BLK)            // 49152
#define SMEM_MBAR_OFF (NSTAGE * STAGE_BYTES)   // 196608
#define SMEM_TOTAL (SMEM_MBAR_OFF + 128)       // 196736

// ============================================================
// Global scratch (static __device__ allowed; no cudaMalloc)
// ============================================================
__device__ float g_y[(size_t)MTOT * NTOT];                              // 128 MB
__device__ __align__(1024) unsigned char g_A[(size_t)MTOT * KTOT * 4];  // 32 MB (hi+lo tiled)
__device__ __align__(1024) unsigned char g_B[(size_t)NTOT * KTOT * 4];  // 64 MB (hi+lo tiled)

// ============================================================
// Helpers
// ============================================================
static __device__ __forceinline__ uint32_t smem_u32(const void* p) {
    uint32_t a;
    asm("{ .reg .u64 t; cvta.to.shared.u64 t, %1; cvt.u32.u64 %0, t; }" : "=r"(a) : "l"(p));
    return a;
}

static __device__ __forceinline__ uint32_t sw128(uint32_t off) {
    return off ^ ((off >> 3) & 0x70);
}

#define MBARRIER_INIT(addr, cnt) \
    asm volatile("mbarrier.init.shared.b64 [%0], %1;" :: "r"(addr), "r"(cnt) : "memory")

#define MBARRIER_ARRIVE(addr) \
    asm volatile("mbarrier.arrive.shared.b64 _, [%0];" :: "r"(addr) : "memory")

#define MBARRIER_EXPECT_TX(addr, bytes) \
    asm volatile("mbarrier.arrive.expect_tx.shared.b64 _, [%0], %1;" \
                 :: "r"(addr), "r"((uint32_t)(bytes)) : "memory")

#define MBARRIER_WAIT_PARITY(addr, par) do {                                        \
    uint32_t _m = (addr); uint32_t _p = (par); uint32_t _done;                      \
    asm volatile(                                                                    \
        "{\n\t.reg .pred p;\n\t"                                                     \
        "mbarrier.try_wait.parity.acquire.cta.shared::cta.b64 p, [%1], %2;\n\t"      \
        "selp.b32 %0, 1, 0, p;\n\t}"                                                 \
        : "=r"(_done) : "r"(_m), "r"(_p) : "memory");                                \
    if (!_done) {                                                                    \
        asm volatile(                                                                \
            "{\n\t.reg .pred P1;\n\t"                                                \
            "WL_%=:\n\t"                                                             \
            "mbarrier.try_wait.parity.acquire.cta.shared::cta.b64 P1, [%0], %1, 0x989680;\n\t" \
            "@P1 bra.uni WD_%=;\n\t"                                                 \
            "bra.uni WL_%=;\n\t"                                                     \
            "WD_%=:\n\t}"                                                            \
            :: "r"(_m), "r"(_p) : "memory");                                         \
    }                                                                                \
} while (0)

#define BULK_G2S(dst, src, bytes, mbar) \
    asm volatile("cp.async.bulk.shared::cluster.global.mbarrier::complete_tx::bytes " \
                 "[%0], [%1], %2, [%3];" \
                 :: "r"(dst), "l"(src), "r"((uint32_t)(bytes)), "r"(mbar) : "memory")

static __device__ __forceinline__ void ldsm4(uint32_t addr, uint32_t* r) {
    asm volatile("ldmatrix.sync.aligned.m8n8.x4.shared.b16 {%0,%1,%2,%3}, [%4];"
                 : "=r"(r[0]), "=r"(r[1]), "=r"(r[2]), "=r"(r[3]) : "r"(addr));
}

static __device__ __forceinline__ void mma16816(float* c, const uint32_t* a, const uint32_t* b) {
    asm volatile(
        "mma.sync.aligned.m16n8k16.row.col.f32.bf16.bf16.f32 "
        "{%0,%1,%2,%3}, {%4,%5,%6,%7}, {%8,%9}, {%0,%1,%2,%3};"
        : "+f"(c[0]), "+f"(c[1]), "+f"(c[2]), "+f"(c[3])
        : "r"(a[0]), "r"(a[1]), "r"(a[2]), "r"(a[3]), "r"(b[0]), "r"(b[1]));
}

static __device__ __forceinline__ uint32_t pack_bf16(__nv_bfloat16 a, __nv_bfloat16 b) {
    uint32_t ua = (uint32_t)__bfloat16_as_ushort(a);
    uint32_t ub = (uint32_t)__bfloat16_as_ushort(b);
    return ua | (ub << 16);
}

// Hardware tanh (MUFU.TANH, sm_75+): one MUFU op.
static __device__ __forceinline__ float tanh_hw(float x) {
    float r;
    asm("tanh.approx.f32 %0, %1;" : "=f"(r) : "f"(x));
    return r;
}

// silu(v) = v * sigmoid(v) = 0.5*v*(1 + tanh(v/2)) : 1 MUFU + 2 FMA
static __device__ __forceinline__ float silu(float v) {
    return 0.5f * v * (1.0f + tanh_hw(0.5f * v));
}

// ============================================================
// Conversion kernel: fp32 -> tiled + SW128-swizzled bf16 hi/lo blocks
//   TLOG: log2(rows per tile)   (A: 7 -> 128, B: 8 -> 256)
//   16 elements/thread: 4 back-to-back LDG.128 (MLP=4 hides DRAM/PTW
//   latency per B300 model), 4 swizzled 16B stores.
// ============================================================
template <int TLOG>
__global__ void __launch_bounds__(256)
convert_tiled_19688130085476(const float* __restrict__ src,
                             unsigned char* __restrict__ dst, int n16)
{
    int i = blockIdx.x * blockDim.x + threadIdx.x;
    if (i >= n16) return;

    const int row = i >> 7;           // KTOT/16 = 128 hexadectets per row
    const int q   = i & 127;
    const int k0  = q * 16;
    const int kc  = k0 >> 5;          // k-chunk (BK=32)
    const int c   = k0 & 31;          // 0 or 16
    const int tile = row >> TLOG;
    const int r    = row & ((1 << TLOG) - 1);

    // 4 independent 16B loads, issued back-to-back
    float4 v0 = __ldg((const float4*)src + 4 * i);
    float4 v1 = __ldg((const float4*)src + 4 * i + 1);
    float4 v2 = __ldg((const float4*)src + 4 * i + 2);
    float4 v3 = __ldg((const float4*)src + 4 * i + 3);
    float f[16] = {v0.x, v0.y, v0.z, v0.w, v1.x, v1.y, v1.z, v1.w,
                   v2.x, v2.y, v2.z, v2.w, v3.x, v3.y, v3.z, v3.w};
    __nv_bfloat16 h[16], l[16];
    #pragma unroll
    for (int j = 0; j < 16; j++) {
        h[j] = __float2bfloat16(f[j]);
        l[j] = __float2bfloat16(f[j] - __bfloat162float(h[j]));
    }

    const size_t base = ((size_t)(tile * NCHUNK + kc)) << (TLOG + 7);
    const uint32_t off_h = (uint32_t)(r * 128 + c * 2);   // 16B aligned
    const uint32_t off_l = off_h + 64;

    uint4 hv0, hv1, lv0, lv1;
    hv0.x = pack_bf16(h[0],  h[1]);  hv0.y = pack_bf16(h[2],  h[3]);
    hv0.z = pack_bf16(h[4],  h[5]);  hv0.w = pack_bf16(h[6],  h[7]);
    hv1.x = pack_bf16(h[8],  h[9]);  hv1.y = pack_bf16(h[10], h[11]);
    hv1.z = pack_bf16(h[12], h[13]); hv1.w = pack_bf16(h[14], h[15]);
    lv0.x = pack_bf16(l[0],  l[1]);  lv0.y = pack_bf16(l[2],  l[3]);
    lv0.z = pack_bf16(l[4],  l[5]);  lv0.w = pack_bf16(l[6],  l[7]);
    lv1.x = pack_bf16(l[8],  l[9]);  lv1.y = pack_bf16(l[10], l[11]);
    lv1.z = pack_bf16(l[12], l[13]); lv1.w = pack_bf16(l[14], l[15]);

    *(uint4*)(dst + base + sw128(off_h))      = hv0;
    *(uint4*)(dst + base + sw128(off_h + 16)) = hv1;
    *(uint4*)(dst + base + sw128(off_l))      = lv0;
    *(uint4*)(dst + base + sw128(off_l + 16)) = lv1;
}

// ============================================================
// GEMM kernel: y = x @ W^T  via 3-term bf16-split HMMA
//   grid (NTOT/BN, MTOT/BM) = (32, 32), 256 threads
//   4-stage producer/consumer mbarrier ring
//   (UNCHANGED — ~780us, ~3% over the HMMA issue wall)
// ============================================================
__global__ void __launch_bounds__(256)
gemm_hmma_19688130085476()
{
    extern __shared__ __align__(1024) char smem[];
    const uint32_t sbase = smem_u32(smem);
    const uint32_t mb_full  = sbase + SMEM_MBAR_OFF;                 // NSTAGE x 8B
    const uint32_t mb_empty = sbase + SMEM_MBAR_OFF + NSTAGE * 8;    // NSTAGE x 8B
    const int tid = threadIdx.x;
    const int wid = tid >> 5;
    const int lid = tid & 31;

    const int n_tile = blockIdx.x;
    const int m_tile = blockIdx.y;
    const int n0 = n_tile * BN;
    const int m0 = m_tile * BM;

    const int warp_m = wid >> 2;   // 0..1 -> 64-row slab
    const int warp_n = wid & 3;    // 0..3 -> 64-col slab

    const int a_row_lane   = (lid & 7) + (((lid >> 3) & 1) << 3);
    const int a_chunk_lane = (lid >> 4) & 1;
    const int b_row_lane   = (lid & 7) + (((lid >> 4) & 1) << 3);
    const int b_chunk_lane = (lid >> 3) & 1;

    float acc[4][8][4];
    #pragma unroll
    for (int i = 0; i < 4; i++)
        #pragma unroll
        for (int j = 0; j < 8; j++)
            #pragma unroll
            for (int e = 0; e < 4; e++) acc[i][j][e] = 0.0f;

    if (tid == 0) {
        #pragma unroll
        for (int s = 0; s < NSTAGE; s++) {
            MBARRIER_INIT(mb_full + s * 8, 1);
            MBARRIER_INIT(mb_empty + s * 8, 8);   // one arrive per warp
        }
    }
    __syncthreads();

    const unsigned char* Abase = g_A + ((size_t)m_tile * NCHUNK) * A_BLK;
    const unsigned char* Bbase = g_B + ((size_t)n_tile * NCHUNK) * B_BLK;

    auto produce = [&](int kc, int slot) {
        const uint32_t mb = mb_full + slot * 8;
        const uint32_t sd = sbase + slot * STAGE_BYTES;
        MBARRIER_EXPECT_TX(mb, STAGE_BYTES);
        BULK_G2S(sd,         Abase + (size_t)kc * A_BLK, A_BLK, mb);
        BULK_G2S(sd + A_BLK, Bbase + (size_t)kc * B_BLK, B_BLK, mb);
    };

    // prologue: fill NSTAGE-1 slots
    if (tid == 0) { produce(0, 0); produce(1, 1); produce(2, 2); }

    for (int kc = 0; kc < NCHUNK; kc++) {
        const int slot = kc % NSTAGE;

        // producer: issue production j = kc + NSTAGE-1 after its slot drains
        if (tid == 0 && kc + (NSTAGE - 1) < NCHUNK) {
            const int j = kc + (NSTAGE - 1);
            MBARRIER_WAIT_PARITY(mb_empty + (j % NSTAGE) * 8,
                                 (uint32_t)(((j / NSTAGE) & 1) ^ 1));
            produce(j, j % NSTAGE);
        }

        // consumer: wait for production kc
        MBARRIER_WAIT_PARITY(mb_full + slot * 8, (uint32_t)((kc / NSTAGE) & 1));

        const uint32_t slotA = sbase + slot * STAGE_BYTES;
        const uint32_t slotB = slotA + A_BLK;
        #pragma unroll
        for (int ks = 0; ks < 2; ks++) {
            uint32_t Ah[4][4], Al[4][4], Bh[4][4], Bl[4][4];
            const int a_chunk = 2 * ks + a_chunk_lane;
            const int b_chunk = 2 * ks + b_chunk_lane;

            #pragma unroll
            for (int tm = 0; tm < 4; tm++) {
                uint32_t row = warp_m * 64 + tm * 16 + a_row_lane;
                uint32_t off = row * 128 + a_chunk * 16;
                ldsm4(slotA + sw128(off),      Ah[tm]);
                ldsm4(slotA + sw128(off + 64), Al[tm]);
            }
            #pragma unroll
            for (int tn = 0; tn < 4; tn++) {
                uint32_t row = warp_n * 64 + tn * 16 + b_row_lane;
                uint32_t off = row * 128 + b_chunk * 16;
                ldsm4(slotB + sw128(off),      Bh[tn]);
                ldsm4(slotB + sw128(off + 64), Bl[tn]);
            }

            #pragma unroll
            for (int tm = 0; tm < 4; tm++)
                #pragma unroll
                for (int tn = 0; tn < 4; tn++) {
                    mma16816(acc[tm][2 * tn],     Ah[tm], &Bh[tn][0]);
                    mma16816(acc[tm][2 * tn + 1], Ah[tm], &Bh[tn][2]);
                    mma16816(acc[tm][2 * tn],     Al[tm], &Bh[tn][0]);
                    mma16816(acc[tm][2 * tn + 1], Al[tm], &Bh[tn][2]);
                    mma16816(acc[tm][2 * tn],     Ah[tm], &Bl[tn][0]);
                    mma16816(acc[tm][2 * tn + 1], Ah[tm], &Bl[tn][2]);
                }
        }

        // this warp is done reading slot kc
        if (lid == 0) MBARRIER_ARRIVE(mb_empty + slot * 8);
    }

    // ---- write accumulators to g_y (default caching) ----
    const int g = lid >> 2, t = lid & 3;
    #pragma unroll
    for (int tm = 0; tm < 4; tm++) {
        int r0 = m0 + warp_m * 64 + tm * 16 + g;
        #pragma unroll
        for (int tn = 0; tn < 8; tn++) {
            int cc = n0 + warp_n * 64 + tn * 8 + 2 * t;
            float2 v0 = make_float2(acc[tm][tn][0], acc[tm][tn][1]);
            float2 v1 = make_float2(acc[tm][tn][2], acc[tm][tn][3]);
            *(float2*)(g_y + (size_t)r0 * NTOT + cc) = v0;
            *(float2*)(g_y + (size_t)(r0 + 8) * NTOT + cc) = v1;
        }
    }
}

// ============================================================
// Epilogue: bias + GroupNorm + SiLU + scale + SiLU
// One WARP per (row, group); 4 coalesced chunks of 128 floats,
// shfl-only reduction, HW-tanh SiLU. L1-bypassing loads/stores
// (__ldcg / __stcg): g_y is read once, out is never re-read.
// ============================================================
__global__ void __launch_bounds__(256, 5)
epilogue_kernel_19688130085476(const float* __restrict__ bias,
                               const float* __restrict__ gn_w,
                               const float* __restrict__ gn_b,
                               const float* __restrict__ mult_w,
                               float* __restrict__ out)
{
    const int blk  = blockIdx.x;          // 0..8191
    const int row  = blk >> 1;
    const int wid  = threadIdx.x >> 5;    // 0..7
    const int lane = threadIdx.x & 31;
    const int g    = (blk & 1) * 8 + wid; // group 0..15
    const int colbase = g * GSZ;

    float4 v[4];
    float s = 0.f, ss = 0.f;
    #pragma unroll
    for (int c4 = 0; c4 < 4; c4++) {
        const int col = colbase + c4 * 128 + lane * 4;
        float4 vv = __ldcg((const float4*)(g_y + (size_t)row * NTOT + col));
        float4 bb = __ldg((const float4*)(bias + col));
        vv.x += bb.x; vv.y += bb.y; vv.z += bb.z; vv.w += bb.w;
        v[c4] = vv;
        s  += vv.x + vv.y + vv.z + vv.w;
        ss += vv.x * vv.x + vv.y * vv.y + vv.z * vv.z + vv.w * vv.w;
    }

    #pragma unroll
    for (int o = 16; o > 0; o >>= 1) {
        s  += __shfl_xor_sync(0xFFFFFFFFu, s, o);
        ss += __shfl_xor_sync(0xFFFFFFFFu, ss, o);
    }

    const float mean = s * (1.0f / GSZ);
    const float var  = ss * (1.0f / GSZ) - mean * mean;
    const float rinv = rsqrtf(var + 1e-5f);

    #pragma unroll
    for (int c4 = 0; c4 < 4; c4++) {
        const int col = colbase + c4 * 128 + lane * 4;
        float4 gw = __ldg((const float4*)(gn_w + col));
        float4 gb = __ldg((const float4*)(gn_b + col));
        float4 mw = __ldg((const float4*)(mult_w + col));
        float vals[4] = {v[c4].x, v[c4].y, v[c4].z, v[c4].w};
        float gws[4]  = {gw.x, gw.y, gw.z, gw.w};
        float gbs[4]  = {gb.x, gb.y, gb.z, gb.w};
        float mws[4]  = {mw.x, mw.y, mw.z, mw.w};
        float res[4];
        #pragma unroll
        for (int j = 0; j < 4; j++) {
            float n = (vals[j] - mean) * rinv * gws[j] + gbs[j];
            float m = silu(n) * mws[j];
            res[j]  = silu(m);
        }
        float4 o4 = make_float4(res[0], res[1], res[2], res[3]);
        __stcg((float4*)(out + (size_t)row * NTOT + col), o4);
    }
}

// ============================================================
// Launch
// ============================================================
extern "C" void kernel_launch(void* const* d_in, const int* in_sizes, int n_in,
                              void* d_out, int out_size)
{
    const float* x      = (const float*)d_in[0];
    const float* W      = (const float*)d_in[1];
    const float* bias   = (const float*)d_in[2];
    const float* gn_w   = (const float*)d_in[3];
    const float* gn_b   = (const float*)d_in[4];
    const float* mult_w = (const float*)d_in[5];
    float* out = (float*)d_out;

    cudaFuncSetAttribute(gemm_hmma_19688130085476,
                         cudaFuncAttributeMaxDynamicSharedMemorySize, SMEM_TOTAL);

    unsigned char *pA, *pB;
    cudaGetSymbolAddress((void**)&pA, g_A);
    cudaGetSymbolAddress((void**)&pB, g_B);

    // 1) split-convert x and W into tiled+swizzled hi/lo blocks
    {
        int n16x = MTOT * KTOT / 16;   // 524,288
        int n16w = NTOT * KTOT / 16;   // 1,048,576
        convert_tiled_19688130085476<7><<<(n16x + 255) / 256, 256>>>(x, pA, n16x);
        convert_tiled_19688130085476<8><<<(n16w + 255) / 256, 256>>>(W, pB, n16w);
    }

    // 2) GEMM
    dim3 grid(NTOT / BN, MTOT / BM);  // (32, 32)
    gemm_hmma_19688130085476<<<grid, 256, SMEM_TOTAL>>>();

    // 3) epilogue
    epilogue_kernel_19688130085476<<<MTOT * 2, 256>>>(bias, gn_w, gn_b, mult_w, out);
}

// round 16
// speedup vs baseline: 1.0087x; 1.0087x over previous
#include <cuda_runtime.h>
#include <cuda_bf16.h>
#include <cstdint>

// ============================================================
// Problem constants
// ============================================================
#define MTOT 4096
#define NTOT 8192
#define KTOT 2048
#define NG   16
#define GSZ  (NTOT / NG)   // 512

// GEMM tiling
#define BM 128
#define BN 256
#define BK 32                    // bf16 K elements per stage
#define NCHUNK (KTOT / BK)       // 64
#define NSTAGE 4

// Tiled+swizzled scratch layout:
//   A block (per m-tile, per k-chunk): 128 rows x 128B ([64B hi | 64B lo]) = 16KB
//   B block (per n-tile, per k-chunk): 256 rows x 128B                     = 32KB
// Rows are SW128-swizzled IN GMEM so a linear bulk copy lands swizzled in SMEM.
#define A_BLK 16384
#define B_BLK 32768
#define STAGE_BYTES (A_BLK + B_BLK)            // 49152
#define SMEM_MBAR_OFF (NSTAGE * STAGE_BYTES)   // 196608
#define SMEM_TOTAL (SMEM_MBAR_OFF + 128)       // 196736

// ============================================================
// Global scratch (static __device__ allowed; no cudaMalloc)
// ============================================================
__device__ float g_y[(size_t)MTOT * NTOT];                              // 128 MB
__device__ __align__(1024) unsigned char g_A[(size_t)MTOT * KTOT * 4];  // 32 MB (hi+lo tiled)
__device__ __align__(1024) unsigned char g_B[(size_t)NTOT * KTOT * 4];  // 64 MB (hi+lo tiled)

// ============================================================
// Helpers
// ============================================================
static __device__ __forceinline__ uint32_t smem_u32(const void* p) {
    uint32_t a;
    asm("{ .reg .u64 t; cvta.to.shared.u64 t, %1; cvt.u32.u64 %0, t; }" : "=r"(a) : "l"(p));
    return a;
}

static __device__ __forceinline__ uint32_t sw128(uint32_t off) {
    return off ^ ((off >> 3) & 0x70);
}

#define MBARRIER_INIT(addr, cnt) \
    asm volatile("mbarrier.init.shared.b64 [%0], %1;" :: "r"(addr), "r"(cnt) : "memory")

#define MBARRIER_ARRIVE(addr) \
    asm volatile("mbarrier.arrive.shared.b64 _, [%0];" :: "r"(addr) : "memory")

#define MBARRIER_EXPECT_TX(addr, bytes) \
    asm volatile("mbarrier.arrive.expect_tx.shared.b64 _, [%0], %1;" \
                 :: "r"(addr), "r"((uint32_t)(bytes)) : "memory")

#define MBARRIER_WAIT_PARITY(addr, par) do {                                        \
    uint32_t _m = (addr); uint32_t _p = (par); uint32_t _done;                      \
    asm volatile(                                                                    \
        "{\n\t.reg .pred p;\n\t"                                                     \
        "mbarrier.try_wait.parity.acquire.cta.shared::cta.b64 p, [%1], %2;\n\t"      \
        "selp.b32 %0, 1, 0, p;\n\t}"                                                 \
        : "=r"(_done) : "r"(_m), "r"(_p) : "memory");                                \
    if (!_done) {                                                                    \
        asm volatile(                                                                \
            "{\n\t.reg .pred P1;\n\t"                                                \
            "WL_%=:\n\t"                                                             \
            "mbarrier.try_wait.parity.acquire.cta.shared::cta.b64 P1, [%0], %1, 0x989680;\n\t" \
            "@P1 bra.uni WD_%=;\n\t"                                                 \
            "bra.uni WL_%=;\n\t"                                                     \
            "WD_%=:\n\t}"                                                            \
            :: "r"(_m), "r"(_p) : "memory");                                         \
    }                                                                                \
} while (0)

#define BULK_G2S(dst, src, bytes, mbar) \
    asm volatile("cp.async.bulk.shared::cluster.global.mbarrier::complete_tx::bytes " \
                 "[%0], [%1], %2, [%3];" \
                 :: "r"(dst), "l"(src), "r"((uint32_t)(bytes)), "r"(mbar) : "memory")

static __device__ __forceinline__ void ldsm4(uint32_t addr, uint32_t* r) {
    asm volatile("ldmatrix.sync.aligned.m8n8.x4.shared.b16 {%0,%1,%2,%3}, [%4];"
                 : "=r"(r[0]), "=r"(r[1]), "=r"(r[2]), "=r"(r[3]) : "r"(addr));
}

static __device__ __forceinline__ void mma16816(float* c, const uint32_t* a, const uint32_t* b) {
    asm volatile(
        "mma.sync.aligned.m16n8k16.row.col.f32.bf16.bf16.f32 "
        "{%0,%1,%2,%3}, {%4,%5,%6,%7}, {%8,%9}, {%0,%1,%2,%3};"
        : "+f"(c[0]), "+f"(c[1]), "+f"(c[2]), "+f"(c[3])
        : "r"(a[0]), "r"(a[1]), "r"(a[2]), "r"(a[3]), "r"(b[0]), "r"(b[1]));
}

static __device__ __forceinline__ uint32_t pack_bf16(__nv_bfloat16 a, __nv_bfloat16 b) {
    uint32_t ua = (uint32_t)__bfloat16_as_ushort(a);
    uint32_t ub = (uint32_t)__bfloat16_as_ushort(b);
    return ua | (ub << 16);
}

// Hardware tanh (MUFU.TANH, sm_75+): one MUFU op.
static __device__ __forceinline__ float tanh_hw(float x) {
    float r;
    asm("tanh.approx.f32 %0, %1;" : "=f"(r) : "f"(x));
    return r;
}

// silu(v) = v * sigmoid(v) = 0.5*v*(1 + tanh(v/2)) : 1 MUFU + 2 FMA
static __device__ __forceinline__ float silu(float v) {
    return 0.5f * v * (1.0f + tanh_hw(0.5f * v));
}

// ============================================================
// Convert body (proven 8-elem version): fp32 -> tiled + SW128-
// swizzled bf16 hi/lo blocks. TLOG: log2(rows/tile).
// ============================================================
template <int TLOG>
static __device__ __forceinline__ void convert_body(
    const float* __restrict__ src, unsigned char* __restrict__ dst, int i)
{
    const int row = i >> 8;           // KTOT/8 = 256 octets per row
    const int q   = i & 255;
    const int k0  = q * 8;
    const int kc  = k0 >> 5;          // k-chunk (BK=32)
    const int c   = k0 & 31;          // 0, 8, 16, 24
    const int tile = row >> TLOG;
    const int r    = row & ((1 << TLOG) - 1);

    float4 v0 = __ldg((const float4*)src + 2 * i);
    float4 v1 = __ldg((const float4*)src + 2 * i + 1);
    float f[8] = {v0.x, v0.y, v0.z, v0.w, v1.x, v1.y, v1.z, v1.w};
    __nv_bfloat16 h[8], l[8];
    #pragma unroll
    for (int j = 0; j < 8; j++) {
        h[j] = __float2bfloat16(f[j]);
        l[j] = __float2bfloat16(f[j] - __bfloat162float(h[j]));
    }

    const size_t base = ((size_t)(tile * NCHUNK + kc)) << (TLOG + 7);
    const uint32_t off_h = (uint32_t)(r * 128 + c * 2);   // 16B aligned
    const uint32_t off_l = off_h + 64;

    uint4 hv, lv;
    hv.x = pack_bf16(h[0], h[1]); hv.y = pack_bf16(h[2], h[3]);
    hv.z = pack_bf16(h[4], h[5]); hv.w = pack_bf16(h[6], h[7]);
    lv.x = pack_bf16(l[0], l[1]); lv.y = pack_bf16(l[2], l[3]);
    lv.z = pack_bf16(l[4], l[5]); lv.w = pack_bf16(l[6], l[7]);
    *(uint4*)(dst + base + sw128(off_h)) = hv;
    *(uint4*)(dst + base + sw128(off_l)) = lv;
}

// Merged convert launch: blocks [0, nblkA) handle x -> g_A (TLOG=7),
// the rest handle W -> g_B (TLOG=8). One launch, better tail packing.
__global__ void __launch_bounds__(256)
convert_both_19688130085476(const float* __restrict__ x,
                            const float* __restrict__ W,
                            unsigned char* __restrict__ dA,
                            unsigned char* __restrict__ dB,
                            int nblkA)
{
    if ((int)blockIdx.x < nblkA) {
        int i = blockIdx.x * blockDim.x + threadIdx.x;   // < MTOT*KTOT/8 exactly
        convert_body<7>(x, dA, i);
    } else {
        int i = (blockIdx.x - nblkA) * blockDim.x + threadIdx.x;  // < NTOT*KTOT/8
        convert_body<8>(W, dB, i);
    }
}

// ============================================================
// GEMM kernel: y = x @ W^T  via 3-term bf16-split HMMA
//   grid (NTOT/BN, MTOT/BM) = (32, 32), 256 threads
//   4-stage producer/consumer mbarrier ring
//   (UNCHANGED — ~780us, ~98% of the HMMA throughput wall)
// ============================================================
__global__ void __launch_bounds__(256)
gemm_hmma_19688130085476()
{
    extern __shared__ __align__(1024) char smem[];
    const uint32_t sbase = smem_u32(smem);
    const uint32_t mb_full  = sbase + SMEM_MBAR_OFF;                 // NSTAGE x 8B
    const uint32_t mb_empty = sbase + SMEM_MBAR_OFF + NSTAGE * 8;    // NSTAGE x 8B
    const int tid = threadIdx.x;
    const int wid = tid >> 5;
    const int lid = tid & 31;

    const int n_tile = blockIdx.x;
    const int m_tile = blockIdx.y;
    const int n0 = n_tile * BN;
    const int m0 = m_tile * BM;

    const int warp_m = wid >> 2;   // 0..1 -> 64-row slab
    const int warp_n = wid & 3;    // 0..3 -> 64-col slab

    const int a_row_lane   = (lid & 7) + (((lid >> 3) & 1) << 3);
    const int a_chunk_lane = (lid >> 4) & 1;
    const int b_row_lane   = (lid & 7) + (((lid >> 4) & 1) << 3);
    const int b_chunk_lane = (lid >> 3) & 1;

    float acc[4][8][4];
    #pragma unroll
    for (int i = 0; i < 4; i++)
        #pragma unroll
        for (int j = 0; j < 8; j++)
            #pragma unroll
            for (int e = 0; e < 4; e++) acc[i][j][e] = 0.0f;

    if (tid == 0) {
        #pragma unroll
        for (int s = 0; s < NSTAGE; s++) {
            MBARRIER_INIT(mb_full + s * 8, 1);
            MBARRIER_INIT(mb_empty + s * 8, 8);   // one arrive per warp
        }
    }
    __syncthreads();

    const unsigned char* Abase = g_A + ((size_t)m_tile * NCHUNK) * A_BLK;
    const unsigned char* Bbase = g_B + ((size_t)n_tile * NCHUNK) * B_BLK;

    auto produce = [&](int kc, int slot) {
        const uint32_t mb = mb_full + slot * 8;
        const uint32_t sd = sbase + slot * STAGE_BYTES;
        MBARRIER_EXPECT_TX(mb, STAGE_BYTES);
        BULK_G2S(sd,         Abase + (size_t)kc * A_BLK, A_BLK, mb);
        BULK_G2S(sd + A_BLK, Bbase + (size_t)kc * B_BLK, B_BLK, mb);
    };

    // prologue: fill NSTAGE-1 slots
    if (tid == 0) { produce(0, 0); produce(1, 1); produce(2, 2); }

    for (int kc = 0; kc < NCHUNK; kc++) {
        const int slot = kc % NSTAGE;

        // producer: issue production j = kc + NSTAGE-1 after its slot drains
        if (tid == 0 && kc + (NSTAGE - 1) < NCHUNK) {
            const int j = kc + (NSTAGE - 1);
            MBARRIER_WAIT_PARITY(mb_empty + (j % NSTAGE) * 8,
                                 (uint32_t)(((j / NSTAGE) & 1) ^ 1));
            produce(j, j % NSTAGE);
        }

        // consumer: wait for production kc
        MBARRIER_WAIT_PARITY(mb_full + slot * 8, (uint32_t)((kc / NSTAGE) & 1));

        const uint32_t slotA = sbase + slot * STAGE_BYTES;
        const uint32_t slotB = slotA + A_BLK;
        #pragma unroll
        for (int ks = 0; ks < 2; ks++) {
            uint32_t Ah[4][4], Al[4][4], Bh[4][4], Bl[4][4];
            const int a_chunk = 2 * ks + a_chunk_lane;
            const int b_chunk = 2 * ks + b_chunk_lane;

            #pragma unroll
            for (int tm = 0; tm < 4; tm++) {
                uint32_t row = warp_m * 64 + tm * 16 + a_row_lane;
                uint32_t off = row * 128 + a_chunk * 16;
                ldsm4(slotA + sw128(off),      Ah[tm]);
                ldsm4(slotA + sw128(off + 64), Al[tm]);
            }
            #pragma unroll
            for (int tn = 0; tn < 4; tn++) {
                uint32_t row = warp_n * 64 + tn * 16 + b_row_lane;
                uint32_t off = row * 128 + b_chunk * 16;
                ldsm4(slotB + sw128(off),      Bh[tn]);
                ldsm4(slotB + sw128(off + 64), Bl[tn]);
            }

            #pragma unroll
            for (int tm = 0; tm < 4; tm++)
                #pragma unroll
                for (int tn = 0; tn < 4; tn++) {
                    mma16816(acc[tm][2 * tn],     Ah[tm], &Bh[tn][0]);
                    mma16816(acc[tm][2 * tn + 1], Ah[tm], &Bh[tn][2]);
                    mma16816(acc[tm][2 * tn],     Al[tm], &Bh[tn][0]);
                    mma16816(acc[tm][2 * tn + 1], Al[tm], &Bh[tn][2]);
                    mma16816(acc[tm][2 * tn],     Ah[tm], &Bl[tn][0]);
                    mma16816(acc[tm][2 * tn + 1], Ah[tm], &Bl[tn][2]);
                }
        }

        // this warp is done reading slot kc
        if (lid == 0) MBARRIER_ARRIVE(mb_empty + slot * 8);
    }

    // ---- write accumulators to g_y (default caching) ----
    const int g = lid >> 2, t = lid & 3;
    #pragma unroll
    for (int tm = 0; tm < 4; tm++) {
        int r0 = m0 + warp_m * 64 + tm * 16 + g;
        #pragma unroll
        for (int tn = 0; tn < 8; tn++) {
            int cc = n0 + warp_n * 64 + tn * 8 + 2 * t;
            float2 v0 = make_float2(acc[tm][tn][0], acc[tm][tn][1]);
            float2 v1 = make_float2(acc[tm][tn][2], acc[tm][tn][3]);
            *(float2*)(g_y + (size_t)r0 * NTOT + cc) = v0;
            *(float2*)(g_y + (size_t)(r0 + 8) * NTOT + cc) = v1;
        }
    }
}

// ============================================================
// Epilogue: bias + GroupNorm + SiLU + scale + SiLU
// One WARP per (row, group); 4 coalesced chunks of 128 floats,
// shfl-only reduction, HW-tanh SiLU. (256,6): regs<=42 for
// 6 blocks/SM -> more DRAM loads in flight (memory-bound now).
// ============================================================
__global__ void __launch_bounds__(256, 6)
epilogue_kernel_19688130085476(const float* __restrict__ bias,
                               const float* __restrict__ gn_w,
                               const float* __restrict__ gn_b,
                               const float* __restrict__ mult_w,
                               float* __restrict__ out)
{
    const int blk  = blockIdx.x;          // 0..8191
    const int row  = blk >> 1;
    const int wid  = threadIdx.x >> 5;    // 0..7
    const int lane = threadIdx.x & 31;
    const int g    = (blk & 1) * 8 + wid; // group 0..15
    const int colbase = g * GSZ;

    float4 v[4];
    float s = 0.f, ss = 0.f;
    #pragma unroll
    for (int c4 = 0; c4 < 4; c4++) {
        const int col = colbase + c4 * 128 + lane * 4;
        float4 vv = *(const float4*)(g_y + (size_t)row * NTOT + col);
        float4 bb = __ldg((const float4*)(bias + col));
        vv.x += bb.x; vv.y += bb.y; vv.z += bb.z; vv.w += bb.w;
        v[c4] = vv;
        s  += vv.x + vv.y + vv.z + vv.w;
        ss += vv.x * vv.x + vv.y * vv.y + vv.z * vv.z + vv.w * vv.w;
    }

    #pragma unroll
    for (int o = 16; o > 0; o >>= 1) {
        s  += __shfl_xor_sync(0xFFFFFFFFu, s, o);
        ss += __shfl_xor_sync(0xFFFFFFFFu, ss, o);
    }

    const float mean = s * (1.0f / GSZ);
    const float var  = ss * (1.0f / GSZ) - mean * mean;
    const float rinv = rsqrtf(var + 1e-5f);

    #pragma unroll
    for (int c4 = 0; c4 < 4; c4++) {
        const int col = colbase + c4 * 128 + lane * 4;
        float4 gw = __ldg((const float4*)(gn_w + col));
        float4 gb = __ldg((const float4*)(gn_b + col));
        float4 mw = __ldg((const float4*)(mult_w + col));
        float vals[4] = {v[c4].x, v[c4].y, v[c4].z, v[c4].w};
        float gws[4]  = {gw.x, gw.y, gw.z, gw.w};
        float gbs[4]  = {gb.x, gb.y, gb.z, gb.w};
        float mws[4]  = {mw.x, mw.y, mw.z, mw.w};
        float res[4];
        #pragma unroll
        for (int j = 0; j < 4; j++) {
            float n = (vals[j] - mean) * rinv * gws[j] + gbs[j];
            float m = silu(n) * mws[j];
            res[j]  = silu(m);
        }
        float4 o4 = make_float4(res[0], res[1], res[2], res[3]);
        *(float4*)(out + (size_t)row * NTOT + col) = o4;
    }
}

// ============================================================
// Launch
// ============================================================
extern "C" void kernel_launch(void* const* d_in, const int* in_sizes, int n_in,
                              void* d_out, int out_size)
{
    const float* x      = (const float*)d_in[0];
    const float* W      = (const float*)d_in[1];
    const float* bias   = (const float*)d_in[2];
    const float* gn_w   = (const float*)d_in[3];
    const float* gn_b   = (const float*)d_in[4];
    const float* mult_w = (const float*)d_in[5];
    float* out = (float*)d_out;

    cudaFuncSetAttribute(gemm_hmma_19688130085476,
                         cudaFuncAttributeMaxDynamicSharedMemorySize, SMEM_TOTAL);

    unsigned char *pA, *pB;
    cudaGetSymbolAddress((void**)&pA, g_A);
    cudaGetSymbolAddress((void**)&pB, g_B);

    // 1) merged split-convert: x -> g_A and W -> g_B in one launch
    {
        const int nblkA = (MTOT * KTOT / 8) / 256;   // 4096 (exact)
        const int nblkB = (NTOT * KTOT / 8) / 256;   // 8192 (exact)
        convert_both_19688130085476<<<nblkA + nblkB, 256>>>(x, W, pA, pB, nblkA);
    }

    // 2) GEMM
    dim3 grid(NTOT / BN, MTOT / BM);  // (32, 32)
    gemm_hmma_19688130085476<<<grid, 256, SMEM_TOTAL>>>();

    // 3) epilogue
    epilogue_kernel_19688130085476<<<MTOT * 2, 256>>>(bias, gn_w, gn_b, mult_w, out);
}

// round 17
// speedup vs baseline: 1.0092x; 1.0004x over previous
#include <cuda_runtime.h>
#include <cuda_bf16.h>
#include <cstdint>

// ============================================================
// Problem constants
// ============================================================
#define MTOT 4096
#define NTOT 8192
#define KTOT 2048
#define NG   16
#define GSZ  (NTOT / NG)   // 512

// GEMM tiling
#define BM 128
#define BN 256
#define BK 32                    // bf16 K elements per stage
#define NCHUNK (KTOT / BK)       // 64
#define NSTAGE 4
#define NTILES ((MTOT / BM) * (NTOT / BN))   // 1024
#define NPERSIST 160             // >= SM count (148 or 152); extras exit

// Tiled+swizzled scratch layout:
//   A block (per m-tile, per k-chunk): 128 rows x 128B ([64B hi | 64B lo]) = 16KB
//   B block (per n-tile, per k-chunk): 256 rows x 128B                     = 32KB
#define A_BLK 16384
#define B_BLK 32768
#define STAGE_BYTES (A_BLK + B_BLK)            // 49152
#define SMEM_MBAR_OFF (NSTAGE * STAGE_BYTES)   // 196608
#define SMEM_TOTAL (SMEM_MBAR_OFF + 128)       // 196736

// ============================================================
// Global scratch (static __device__ allowed; no cudaMalloc)
// ============================================================
__device__ float g_y[(size_t)MTOT * NTOT];                              // 128 MB
__device__ __align__(1024) unsigned char g_A[(size_t)MTOT * KTOT * 4];  // 32 MB
__device__ __align__(1024) unsigned char g_B[(size_t)NTOT * KTOT * 4];  // 64 MB
__device__ int g_tile_ctr;                                              // reset per launch

// ============================================================
// Helpers
// ============================================================
static __device__ __forceinline__ uint32_t smem_u32(const void* p) {
    uint32_t a;
    asm("{ .reg .u64 t; cvta.to.shared.u64 t, %1; cvt.u32.u64 %0, t; }" : "=r"(a) : "l"(p));
    return a;
}

static __device__ __forceinline__ uint32_t sw128(uint32_t off) {
    return off ^ ((off >> 3) & 0x70);
}

#define MBARRIER_INIT(addr, cnt) \
    asm volatile("mbarrier.init.shared.b64 [%0], %1;" :: "r"(addr), "r"(cnt) : "memory")

#define MBARRIER_ARRIVE(addr) \
    asm volatile("mbarrier.arrive.shared.b64 _, [%0];" :: "r"(addr) : "memory")

#define MBARRIER_EXPECT_TX(addr, bytes) \
    asm volatile("mbarrier.arrive.expect_tx.shared.b64 _, [%0], %1;" \
                 :: "r"(addr), "r"((uint32_t)(bytes)) : "memory")

#define MBARRIER_WAIT_PARITY(addr, par) do {                                        \
    uint32_t _m = (addr); uint32_t _p = (par); uint32_t _done;                      \
    asm volatile(                                                                    \
        "{\n\t.reg .pred p;\n\t"                                                     \
        "mbarrier.try_wait.parity.acquire.cta.shared::cta.b64 p, [%1], %2;\n\t"      \
        "selp.b32 %0, 1, 0, p;\n\t}"                                                 \
        : "=r"(_done) : "r"(_m), "r"(_p) : "memory");                                \
    if (!_done) {                                                                    \
        asm volatile(                                                                \
            "{\n\t.reg .pred P1;\n\t"                                                \
            "WL_%=:\n\t"                                                             \
            "mbarrier.try_wait.parity.acquire.cta.shared::cta.b64 P1, [%0], %1, 0x989680;\n\t" \
            "@P1 bra.uni WD_%=;\n\t"                                                 \
            "bra.uni WL_%=;\n\t"                                                     \
            "WD_%=:\n\t}"                                                            \
            :: "r"(_m), "r"(_p) : "memory");                                         \
    }                                                                                \
} while (0)

#define BULK_G2S(dst, src, bytes, mbar) \
    asm volatile("cp.async.bulk.shared::cluster.global.mbarrier::complete_tx::bytes " \
                 "[%0], [%1], %2, [%3];" \
                 :: "r"(dst), "l"(src), "r"((uint32_t)(bytes)), "r"(mbar) : "memory")

static __device__ __forceinline__ void ldsm4(uint32_t addr, uint32_t* r) {
    asm volatile("ldmatrix.sync.aligned.m8n8.x4.shared.b16 {%0,%1,%2,%3}, [%4];"
                 : "=r"(r[0]), "=r"(r[1]), "=r"(r[2]), "=r"(r[3]) : "r"(addr));
}

static __device__ __forceinline__ void mma16816(float* c, const uint32_t* a, const uint32_t* b) {
    asm volatile(
        "mma.sync.aligned.m16n8k16.row.col.f32.bf16.bf16.f32 "
        "{%0,%1,%2,%3}, {%4,%5,%6,%7}, {%8,%9}, {%0,%1,%2,%3};"
        : "+f"(c[0]), "+f"(c[1]), "+f"(c[2]), "+f"(c[3])
        : "r"(a[0]), "r"(a[1]), "r"(a[2]), "r"(a[3]), "r"(b[0]), "r"(b[1]));
}

static __device__ __forceinline__ uint32_t pack_bf16(__nv_bfloat16 a, __nv_bfloat16 b) {
    uint32_t ua = (uint32_t)__bfloat16_as_ushort(a);
    uint32_t ub = (uint32_t)__bfloat16_as_ushort(b);
    return ua | (ub << 16);
}

// Hardware tanh (MUFU.TANH, sm_75+): one MUFU op.
static __device__ __forceinline__ float tanh_hw(float x) {
    float r;
    asm("tanh.approx.f32 %0, %1;" : "=f"(r) : "f"(x));
    return r;
}

// silu(v) = v * sigmoid(v) = 0.5*v*(1 + tanh(v/2)) : 1 MUFU + 2 FMA
static __device__ __forceinline__ float silu(float v) {
    return 0.5f * v * (1.0f + tanh_hw(0.5f * v));
}

// ============================================================
// Convert body: fp32 -> tiled + SW128-swizzled bf16 hi/lo blocks.
// ============================================================
template <int TLOG>
static __device__ __forceinline__ void convert_body(
    const float* __restrict__ src, unsigned char* __restrict__ dst, int i)
{
    const int row = i >> 8;           // KTOT/8 = 256 octets per row
    const int q   = i & 255;
    const int k0  = q * 8;
    const int kc  = k0 >> 5;          // k-chunk (BK=32)
    const int c   = k0 & 31;          // 0, 8, 16, 24
    const int tile = row >> TLOG;
    const int r    = row & ((1 << TLOG) - 1);

    float4 v0 = __ldg((const float4*)src + 2 * i);
    float4 v1 = __ldg((const float4*)src + 2 * i + 1);
    float f[8] = {v0.x, v0.y, v0.z, v0.w, v1.x, v1.y, v1.z, v1.w};
    __nv_bfloat16 h[8], l[8];
    #pragma unroll
    for (int j = 0; j < 8; j++) {
        h[j] = __float2bfloat16(f[j]);
        l[j] = __float2bfloat16(f[j] - __bfloat162float(h[j]));
    }

    const size_t base = ((size_t)(tile * NCHUNK + kc)) << (TLOG + 7);
    const uint32_t off_h = (uint32_t)(r * 128 + c * 2);   // 16B aligned
    const uint32_t off_l = off_h + 64;

    uint4 hv, lv;
    hv.x = pack_bf16(h[0], h[1]); hv.y = pack_bf16(h[2], h[3]);
    hv.z = pack_bf16(h[4], h[5]); hv.w = pack_bf16(h[6], h[7]);
    lv.x = pack_bf16(l[0], l[1]); lv.y = pack_bf16(l[2], l[3]);
    lv.z = pack_bf16(l[4], l[5]); lv.w = pack_bf16(l[6], l[7]);
    *(uint4*)(dst + base + sw128(off_h)) = hv;
    *(uint4*)(dst + base + sw128(off_l)) = lv;
}

__global__ void __launch_bounds__(256)
convert_both_19688130085476(const float* __restrict__ x,
                            const float* __restrict__ W,
                            unsigned char* __restrict__ dA,
                            unsigned char* __restrict__ dB,
                            int nblkA)
{
    if ((int)blockIdx.x < nblkA) {
        int i = blockIdx.x * blockDim.x + threadIdx.x;
        convert_body<7>(x, dA, i);
    } else {
        int i = (blockIdx.x - nblkA) * blockDim.x + threadIdx.x;
        convert_body<8>(W, dB, i);
    }
}

// ============================================================
// Persistent GEMM: y = x @ W^T via 3-term bf16-split HMMA
//   grid = NPERSIST, each CTA steals tiles from g_tile_ctr.
//   The mbarrier ring is CONTINUOUS across tiles (global chunk
//   index j; parity formulas compose since 64 % NSTAGE == 0).
//   Next tile grabbed one tile ahead -> producer pre-fills its
//   stages during chunks 61-63, overlapping the store tail.
// ============================================================
__global__ void __launch_bounds__(256)
gemm_hmma_19688130085476()
{
    extern __shared__ __align__(1024) char smem[];
    const uint32_t sbase = smem_u32(smem);
    const uint32_t mb_full  = sbase + SMEM_MBAR_OFF;                 // NSTAGE x 8B
    const uint32_t mb_empty = sbase + SMEM_MBAR_OFF + NSTAGE * 8;    // NSTAGE x 8B
    const int tid = threadIdx.x;
    const int wid = tid >> 5;
    const int lid = tid & 31;

    const int warp_m = wid >> 2;   // 0..1 -> 64-row slab
    const int warp_n = wid & 3;    // 0..3 -> 64-col slab

    const int a_row_lane   = (lid & 7) + (((lid >> 3) & 1) << 3);
    const int a_chunk_lane = (lid >> 4) & 1;
    const int b_row_lane   = (lid & 7) + (((lid >> 4) & 1) << 3);
    const int b_chunk_lane = (lid >> 3) & 1;

    float acc[4][8][4];
    #pragma unroll
    for (int i = 0; i < 4; i++)
        #pragma unroll
        for (int j = 0; j < 8; j++)
            #pragma unroll
            for (int e = 0; e < 4; e++) acc[i][j][e] = 0.0f;

    __shared__ int s_cur, s_next;
    if (tid == 0) {
        #pragma unroll
        for (int s = 0; s < NSTAGE; s++) {
            MBARRIER_INIT(mb_full + s * 8, 1);
            MBARRIER_INIT(mb_empty + s * 8, 8);   // one arrive per warp
        }
        s_cur  = atomicAdd(&g_tile_ctr, 1);
        s_next = atomicAdd(&g_tile_ctr, 1);
    }
    __syncthreads();

    int cur = s_cur;
    if (cur >= NTILES) return;      // surplus persistent CTA: no work
    int nxt = s_next;

    // produce chunk kc_p of tile tt, global production index j
    auto produce = [&](int tt, int kc_p, int j) {
        const int slot = j & 3;
        const uint32_t mb = mb_full + slot * 8;
        const uint32_t sd = sbase + slot * STAGE_BYTES;
        const int mt = tt >> 5, nt = tt & 31;
        MBARRIER_EXPECT_TX(mb, STAGE_BYTES);
        BULK_G2S(sd,         g_A + ((size_t)(mt * NCHUNK + kc_p)) * A_BLK, A_BLK, mb);
        BULK_G2S(sd + A_BLK, g_B + ((size_t)(nt * NCHUNK + kc_p)) * B_BLK, B_BLK, mb);
    };

    // prologue: fill NSTAGE-1 slots with tile cur's chunks 0..2
    if (tid == 0) { produce(cur, 0, 0); produce(cur, 1, 1); produce(cur, 2, 2); }

    int cbase = 0;   // global chunk index base of current tile
    while (true) {
        for (int kc = 0; kc < NCHUNK; kc++) {
            const int jc = cbase + kc;          // global consume index
            const int slot = jc & 3;

            // producer: production j = jc + 3 (tile cur if kc+3<64, else nxt)
            if (tid == 0) {
                const int j  = jc + 3;
                const int jt = kc + 3;
                const int ptile = (jt < NCHUNK) ? cur : nxt;
                if (ptile < NTILES) {
                    MBARRIER_WAIT_PARITY(mb_empty + (j & 3) * 8,
                                         (uint32_t)(((j >> 2) & 1) ^ 1));
                    produce(ptile, (jt < NCHUNK) ? jt : jt - NCHUNK, j);
                }
            }

            // consumer: wait for production jc
            MBARRIER_WAIT_PARITY(mb_full + slot * 8, (uint32_t)((jc >> 2) & 1));

            const uint32_t slotA = sbase + slot * STAGE_BYTES;
            const uint32_t slotB = slotA + A_BLK;
            #pragma unroll
            for (int ks = 0; ks < 2; ks++) {
                uint32_t Ah[4][4], Al[4][4], Bh[4][4], Bl[4][4];
                const int a_chunk = 2 * ks + a_chunk_lane;
                const int b_chunk = 2 * ks + b_chunk_lane;

                #pragma unroll
                for (int tm = 0; tm < 4; tm++) {
                    uint32_t row = warp_m * 64 + tm * 16 + a_row_lane;
                    uint32_t off = row * 128 + a_chunk * 16;
                    ldsm4(slotA + sw128(off),      Ah[tm]);
                    ldsm4(slotA + sw128(off + 64), Al[tm]);
                }
                #pragma unroll
                for (int tn = 0; tn < 4; tn++) {
                    uint32_t row = warp_n * 64 + tn * 16 + b_row_lane;
                    uint32_t off = row * 128 + b_chunk * 16;
                    ldsm4(slotB + sw128(off),      Bh[tn]);
                    ldsm4(slotB + sw128(off + 64), Bl[tn]);
                }

                #pragma unroll
                for (int tm = 0; tm < 4; tm++)
                    #pragma unroll
                    for (int tn = 0; tn < 4; tn++) {
                        mma16816(acc[tm][2 * tn],     Ah[tm], &Bh[tn][0]);
                        mma16816(acc[tm][2 * tn + 1], Ah[tm], &Bh[tn][2]);
                        mma16816(acc[tm][2 * tn],     Al[tm], &Bh[tn][0]);
                        mma16816(acc[tm][2 * tn + 1], Al[tm], &Bh[tn][2]);
                        mma16816(acc[tm][2 * tn],     Ah[tm], &Bl[tn][0]);
                        mma16816(acc[tm][2 * tn + 1], Ah[tm], &Bl[tn][2]);
                    }
            }

            if (lid == 0) MBARRIER_ARRIVE(mb_empty + slot * 8);
        }

        // ---- store this tile's accumulators to g_y; overlaps with the
        //      already-in-flight bulk copies of the next tile ----
        {
            const int m0 = (cur >> 5) * BM;
            const int n0 = (cur & 31) * BN;
            const int g = lid >> 2, t = lid & 3;
            #pragma unroll
            for (int tm = 0; tm < 4; tm++) {
                int r0 = m0 + warp_m * 64 + tm * 16 + g;
                #pragma unroll
                for (int tn = 0; tn < 8; tn++) {
                    int cc = n0 + warp_n * 64 + tn * 8 + 2 * t;
                    float2 v0 = make_float2(acc[tm][tn][0], acc[tm][tn][1]);
                    float2 v1 = make_float2(acc[tm][tn][2], acc[tm][tn][3]);
                    *(float2*)(g_y + (size_t)r0 * NTOT + cc) = v0;
                    *(float2*)(g_y + (size_t)(r0 + 8) * NTOT + cc) = v1;
                }
            }
            #pragma unroll
            for (int i = 0; i < 4; i++)
                #pragma unroll
                for (int j = 0; j < 8; j++)
                    #pragma unroll
                    for (int e = 0; e < 4; e++) acc[i][j][e] = 0.0f;
        }

        cbase += NCHUNK;
        cur = nxt;
        if (cur >= NTILES) break;
        if (tid == 0) s_next = atomicAdd(&g_tile_ctr, 1);
        __syncthreads();            // publish s_next before next boundary read
        nxt = s_next;
    }
}

// ============================================================
// Epilogue: bias + GroupNorm + SiLU + scale + SiLU
// One WARP per (row, group); shfl-only reduction, HW-tanh SiLU.
// ============================================================
__global__ void __launch_bounds__(256, 6)
epilogue_kernel_19688130085476(const float* __restrict__ bias,
                               const float* __restrict__ gn_w,
                               const float* __restrict__ gn_b,
                               const float* __restrict__ mult_w,
                               float* __restrict__ out)
{
    const int blk  = blockIdx.x;          // 0..8191
    const int row  = blk >> 1;
    const int wid  = threadIdx.x >> 5;    // 0..7
    const int lane = threadIdx.x & 31;
    const int g    = (blk & 1) * 8 + wid; // group 0..15
    const int colbase = g * GSZ;

    float4 v[4];
    float s = 0.f, ss = 0.f;
    #pragma unroll
    for (int c4 = 0; c4 < 4; c4++) {
        const int col = colbase + c4 * 128 + lane * 4;
        float4 vv = *(const float4*)(g_y + (size_t)row * NTOT + col);
        float4 bb = __ldg((const float4*)(bias + col));
        vv.x += bb.x; vv.y += bb.y; vv.z += bb.z; vv.w += bb.w;
        v[c4] = vv;
        s  += vv.x + vv.y + vv.z + vv.w;
        ss += vv.x * vv.x + vv.y * vv.y + vv.z * vv.z + vv.w * vv.w;
    }

    #pragma unroll
    for (int o = 16; o > 0; o >>= 1) {
        s  += __shfl_xor_sync(0xFFFFFFFFu, s, o);
        ss += __shfl_xor_sync(0xFFFFFFFFu, ss, o);
    }

    const float mean = s * (1.0f / GSZ);
    const float var  = ss * (1.0f / GSZ) - mean * mean;
    const float rinv = rsqrtf(var + 1e-5f);

    #pragma unroll
    for (int c4 = 0; c4 < 4; c4++) {
        const int col = colbase + c4 * 128 + lane * 4;
        float4 gw = __ldg((const float4*)(gn_w + col));
        float4 gb = __ldg((const float4*)(gn_b + col));
        float4 mw = __ldg((const float4*)(mult_w + col));
        float vals[4] = {v[c4].x, v[c4].y, v[c4].z, v[c4].w};
        float gws[4]  = {gw.x, gw.y, gw.z, gw.w};
        float gbs[4]  = {gb.x, gb.y, gb.z, gb.w};
        float mws[4]  = {mw.x, mw.y, mw.z, mw.w};
        float res[4];
        #pragma unroll
        for (int j = 0; j < 4; j++) {
            float n = (vals[j] - mean) * rinv * gws[j] + gbs[j];
            float m = silu(n) * mws[j];
            res[j]  = silu(m);
        }
        float4 o4 = make_float4(res[0], res[1], res[2], res[3]);
        *(float4*)(out + (size_t)row * NTOT + col) = o4;
    }
}

// ============================================================
// Launch
// ============================================================
extern "C" void kernel_launch(void* const* d_in, const int* in_sizes, int n_in,
                              void* d_out, int out_size)
{
    const float* x      = (const float*)d_in[0];
    const float* W      = (const float*)d_in[1];
    const float* bias   = (const float*)d_in[2];
    const float* gn_w   = (const float*)d_in[3];
    const float* gn_b   = (const float*)d_in[4];
    const float* mult_w = (const float*)d_in[5];
    float* out = (float*)d_out;

    cudaFuncSetAttribute(gemm_hmma_19688130085476,
                         cudaFuncAttributeMaxDynamicSharedMemorySize, SMEM_TOTAL);

    unsigned char *pA, *pB;
    void* pctr;
    cudaGetSymbolAddress((void**)&pA, g_A);
    cudaGetSymbolAddress((void**)&pB, g_B);
    cudaGetSymbolAddress(&pctr, g_tile_ctr);

    // 0) reset the persistent-GEMM tile counter (graph-legal memset node)
    cudaMemsetAsync(pctr, 0, sizeof(int));

    // 1) merged split-convert: x -> g_A and W -> g_B in one launch
    {
        const int nblkA = (MTOT * KTOT / 8) / 256;   // 4096 (exact)
        const int nblkB = (NTOT * KTOT / 8) / 256;   // 8192 (exact)
        convert_both_19688130085476<<<nblkA + nblkB, 256>>>(x, W, pA, pB, nblkA);
    }

    // 2) persistent GEMM
    gemm_hmma_19688130085476<<<NPERSIST, 256, SMEM_TOTAL>>>();

    // 3) epilogue
    epilogue_kernel_19688130085476<<<MTOT * 2, 256>>>(bias, gn_w, gn_b, mult_w, out);
}